// round 12
// baseline (speedup 1.0000x reference)
#include <cuda_runtime.h>
#include <cuda_fp16.h>
#include <cstdint>
#include <cstring>
#include <math.h>

#define N_NODES 100000
#define N_EDGES 1600000
#define F_IN    256
#define HID     64

// -------- scratch (no device allocations allowed) --------
__device__ int    g_degi  [N_NODES];
__device__ float  g_dinv  [N_NODES];
__device__ int    g_rstart[N_NODES];
__device__ int    g_cursor[N_NODES];
__device__ int    g_bsum  [512];
__device__ int    g_csr   [N_EDGES];
__device__ __half g_h     [(size_t)N_NODES * HID];   // fp16 feature table (gather-optimized)
__device__ float  g_x2    [(size_t)N_NODES * HID];
__device__ float  g_h3    [(size_t)N_NODES * 2];

// register-safe packed-half2 -> float2 (memcpy bitcast always lowers to mov)
__device__ __forceinline__ float2 h2f2(uint32_t u) {
    __half2 h;
    memcpy(&h, &u, 4);
    return __half22float2(h);
}

// -------------------- degree --------------------
__global__ void k_zero_deg(int* __restrict__ deg, int n) {
    int i = blockIdx.x * blockDim.x + threadIdx.x;
    if (i < n) deg[i] = 0;
}

__global__ void k_count_deg(const int* __restrict__ dst, int* __restrict__ deg, int e) {
    int i = blockIdx.x * blockDim.x + threadIdx.x;
    if (i < e) atomicAdd(&deg[dst[i]], 1);
}

// -------------------- block-level exclusive scan over deg --------------------
__global__ void k_scan_block(const int* __restrict__ deg, int* __restrict__ rstart,
                             int* __restrict__ bsum, int n) {
    __shared__ int sm[256];
    int i = blockIdx.x * 256 + threadIdx.x;
    int v = (i < n) ? deg[i] : 0;
    sm[threadIdx.x] = v;
    __syncthreads();
    #pragma unroll
    for (int off = 1; off < 256; off <<= 1) {
        int t = (threadIdx.x >= off) ? sm[threadIdx.x - off] : 0;
        __syncthreads();
        sm[threadIdx.x] += t;
        __syncthreads();
    }
    if (i < n) rstart[i] = sm[threadIdx.x] - v;       // exclusive within block
    if (threadIdx.x == 255) bsum[blockIdx.x] = sm[255];
}

// add per-block global offset (reduced from raw bsum) + init cursor + dinv (fused)
__global__ void k_add_off(int* __restrict__ rstart, int* __restrict__ cursor,
                          const int* __restrict__ bsum, const int* __restrict__ degi,
                          float* __restrict__ dinv, int n) {
    __shared__ int sm[256];
    int b = blockIdx.x;
    int t = threadIdx.x;
    int v = 0;
    for (int j = t; j < b; j += 256) v += bsum[j];
    sm[t] = v;
    __syncthreads();
    #pragma unroll
    for (int off = 128; off > 0; off >>= 1) {
        if (t < off) sm[t] += sm[t + off];
        __syncthreads();
    }
    int off0 = sm[0];
    int i = b * 256 + t;
    if (i < n) {
        int val = rstart[i] + off0;
        rstart[i] = val;
        cursor[i] = val;
        dinv[i] = rsqrtf((float)(degi[i] + 1));   // +1 self-loop
    }
}

__global__ void k_build_csr(const int* __restrict__ src, const int* __restrict__ dst,
                            int* __restrict__ cursor, int* __restrict__ csr, int e) {
    int i = blockIdx.x * blockDim.x + threadIdx.x;
    if (i < e) {
        int p = atomicAdd(&cursor[dst[i]], 1);
        csr[p] = src[i];
    }
}

// -------------------- helpers for tf32 MMA --------------------
__device__ __forceinline__ uint32_t f2tf32(float f) {
    uint32_t u;
    asm("cvt.rna.tf32.f32 %0, %1;" : "=r"(u) : "f"(f));
    return u;
}
__device__ __forceinline__ uint4 cvt4(float4 v) {
    return make_uint4(f2tf32(v.x), f2tf32(v.y), f2tf32(v.z), f2tf32(v.w));
}

// -------------------- tf32 tensor-core GEMM, BM=64 high-occupancy ----------------------
// hout[m,0:64] = half( (A[m,:]@W) * (SCALED ? dinv[m] : 1) )
// BM=64, BN=64, BK=32; 256 threads = 8 warps (4 M x 2 N), warp tile 16x32.
// 3 CTAs/SM (launch_bounds cap) + register prefetch -> higher DRAM MLP.
template <int K, bool SCALED>
__global__ __launch_bounds__(256, 3) void k_gemm_tc(
        const float* __restrict__ A, const float* __restrict__ W,
        const float* __restrict__ dinv, __half* __restrict__ hout, int M) {
    __shared__ uint32_t As[64][36];    // [m][k], stride 36: conflict-free frags
    __shared__ uint32_t Bs[32][72];    // [k][n], stride 72: conflict-free frags

    const int tid  = threadIdx.x;
    const int lane = tid & 31;
    const int warp = tid >> 5;
    const int wm   = warp & 3;         // M warp 0..3 (16 rows each)
    const int wn   = warp >> 2;        // N warp 0..1 (32 cols each)
    const int g    = lane >> 2;        // groupID 0..7
    const int t    = lane & 3;         // thread-in-group 0..3
    const int row0 = blockIdx.x * 64;

    int am[2], ak[2];
    #pragma unroll
    for (int l = 0; l < 2; l++) {
        int i = tid + l * 256;          // 0..511 float4 slots of A tile (64x32)
        am[l] = i >> 3;
        ak[l] = (i & 7) << 2;
    }
    int bk[2], bn[2];
    #pragma unroll
    for (int l = 0; l < 2; l++) {
        int i = tid + l * 256;          // 0..511 float4 slots of B tile (32x64)
        bk[l] = i >> 4;
        bn[l] = (i & 15) << 2;
    }

    float4 ra[2], rb[2];
    float c[4][4] = {};                // [n-tile 8][frag]; warp tile 16x32

    #pragma unroll
    for (int l = 0; l < 2; l++) {
        int gr = row0 + am[l];
        ra[l] = (gr < M) ? *(const float4*)(A + (size_t)gr * K + ak[l])
                         : make_float4(0.f, 0.f, 0.f, 0.f);
    }
    #pragma unroll
    for (int l = 0; l < 2; l++)
        rb[l] = *(const float4*)(W + (size_t)bk[l] * 64 + bn[l]);

    constexpr int NT = K / 32;
    #pragma unroll
    for (int kt = 0; kt < NT; kt++) {
        #pragma unroll
        for (int l = 0; l < 2; l++)
            *(uint4*)&As[am[l]][ak[l]] = cvt4(ra[l]);
        #pragma unroll
        for (int l = 0; l < 2; l++)
            *(uint4*)&Bs[bk[l]][bn[l]] = cvt4(rb[l]);
        __syncthreads();

        if (kt + 1 < NT) {
            int k0 = (kt + 1) * 32;
            #pragma unroll
            for (int l = 0; l < 2; l++) {
                int gr = row0 + am[l];
                ra[l] = (gr < M) ? *(const float4*)(A + (size_t)gr * K + k0 + ak[l])
                                 : make_float4(0.f, 0.f, 0.f, 0.f);
            }
            #pragma unroll
            for (int l = 0; l < 2; l++)
                rb[l] = *(const float4*)(W + (size_t)(k0 + bk[l]) * 64 + bn[l]);
        }

        #pragma unroll
        for (int kc = 0; kc < 4; kc++) {
            int kb = kc * 8;
            int mb = wm * 16;
            uint32_t a0 = As[mb + g    ][kb + t    ];
            uint32_t a1 = As[mb + g + 8][kb + t    ];
            uint32_t a2 = As[mb + g    ][kb + t + 4];
            uint32_t a3 = As[mb + g + 8][kb + t + 4];
            uint32_t bfr[4][2];
            #pragma unroll
            for (int j = 0; j < 4; j++) {
                int nb = wn * 32 + j * 8;
                bfr[j][0] = Bs[kb + t    ][nb + g];
                bfr[j][1] = Bs[kb + t + 4][nb + g];
            }
            #pragma unroll
            for (int j = 0; j < 4; j++) {
                asm volatile(
                    "mma.sync.aligned.m16n8k8.row.col.f32.tf32.tf32.f32 "
                    "{%0,%1,%2,%3}, {%4,%5,%6,%7}, {%8,%9}, {%0,%1,%2,%3};"
                    : "+f"(c[j][0]), "+f"(c[j][1]), "+f"(c[j][2]), "+f"(c[j][3])
                    : "r"(a0), "r"(a1), "r"(a2), "r"(a3),
                      "r"(bfr[j][0]), "r"(bfr[j][1]));
            }
        }
        __syncthreads();
    }

    // epilogue: c0,c1 -> row g; c2,c3 -> row g+8; cols 2t, 2t+1
    {
        int r0 = row0 + wm * 16 + g;
        float d0 = (SCALED && r0 < M)     ? dinv[r0]     : 1.0f;
        float d1 = (SCALED && r0 + 8 < M) ? dinv[r0 + 8] : 1.0f;
        #pragma unroll
        for (int j = 0; j < 4; j++) {
            int col = wn * 32 + j * 8 + 2 * t;
            if (r0 < M)
                *(__half2*)(hout + (size_t)r0 * 64 + col) =
                    __floats2half2_rn(c[j][0] * d0, c[j][1] * d0);
            if (r0 + 8 < M)
                *(__half2*)(hout + (size_t)(r0 + 8) * 64 + col) =
                    __floats2half2_rn(c[j][2] * d1, c[j][3] * d1);
        }
    }
}

// -------------------- pull aggregation + fused epilogue (64 fp16 features) ----------------
// 16 threads per node, 4 features each (8B per lane -> 128B per edge); fp32 accumulators.
// NSCALE=true:  h is UNSCALED (layer 1): neighbor rows scaled by dinv[u], self by dinv[node].
// FUSE3=true:   compute h3[node][0:2] = (relu_row @ W3) * dinv[node] via 16-lane shfl.
template <bool NSCALE, bool FUSE3>
__global__ void k_pull64(const int* __restrict__ rstart, const int* __restrict__ degi,
                         const int* __restrict__ csr, const __half* __restrict__ h,
                         const float* __restrict__ dinv, const float* __restrict__ b,
                         const float* __restrict__ W3, float* __restrict__ out,
                         float* __restrict__ h3, int n) {
    int gid  = blockIdx.x * blockDim.x + threadIdx.x;
    int node = gid >> 4;
    if (node >= n) return;
    int lane16 = gid & 15;
    int c = lane16 << 2;

    int s0  = __ldg(&rstart[node]);
    int cnt = __ldg(&degi[node]);
    float dn = dinv[node];

    // self-loop term
    float4 acc;
    {
        uint2 raw = *(const uint2*)(h + (size_t)node * 64 + c);
        float2 f01 = h2f2(raw.x);
        float2 f23 = h2f2(raw.y);
        acc = make_float4(f01.x, f01.y, f23.x, f23.y);
    }
    if (NSCALE) { acc.x *= dn; acc.y *= dn; acc.z *= dn; acc.w *= dn; }

    int e = 0;
    for (; e + 4 <= cnt; e += 4) {
        int u0 = __ldg(&csr[s0 + e + 0]);
        int u1 = __ldg(&csr[s0 + e + 1]);
        int u2 = __ldg(&csr[s0 + e + 2]);
        int u3 = __ldg(&csr[s0 + e + 3]);
        uint2 r0 = *(const uint2*)(h + (size_t)u0 * 64 + c);
        uint2 r1 = *(const uint2*)(h + (size_t)u1 * 64 + c);
        uint2 r2 = *(const uint2*)(h + (size_t)u2 * 64 + c);
        uint2 r3 = *(const uint2*)(h + (size_t)u3 * 64 + c);
        float2 a01 = h2f2(r0.x), a23 = h2f2(r0.y);
        float2 b01 = h2f2(r1.x), b23 = h2f2(r1.y);
        float2 c01 = h2f2(r2.x), c23 = h2f2(r2.y);
        float2 d01 = h2f2(r3.x), d23 = h2f2(r3.y);
        if (NSCALE) {
            float s0f = __ldg(&dinv[u0]), s1f = __ldg(&dinv[u1]);
            float s2f = __ldg(&dinv[u2]), s3f = __ldg(&dinv[u3]);
            acc.x += a01.x * s0f + b01.x * s1f + c01.x * s2f + d01.x * s3f;
            acc.y += a01.y * s0f + b01.y * s1f + c01.y * s2f + d01.y * s3f;
            acc.z += a23.x * s0f + b23.x * s1f + c23.x * s2f + d23.x * s3f;
            acc.w += a23.y * s0f + b23.y * s1f + c23.y * s2f + d23.y * s3f;
        } else {
            acc.x += a01.x + b01.x + c01.x + d01.x;
            acc.y += a01.y + b01.y + c01.y + d01.y;
            acc.z += a23.x + b23.x + c23.x + d23.x;
            acc.w += a23.y + b23.y + c23.y + d23.y;
        }
    }
    for (; e < cnt; e++) {
        int u = __ldg(&csr[s0 + e]);
        uint2 raw = *(const uint2*)(h + (size_t)u * 64 + c);
        float2 f01 = h2f2(raw.x);
        float2 f23 = h2f2(raw.y);
        float d = NSCALE ? __ldg(&dinv[u]) : 1.0f;
        acc.x += f01.x * d; acc.y += f01.y * d; acc.z += f23.x * d; acc.w += f23.y * d;
    }

    float4 bb = *(const float4*)(b + c);
    float4 o;
    o.x = fmaxf(dn * acc.x + bb.x, 0.f);
    o.y = fmaxf(dn * acc.y + bb.y, 0.f);
    o.z = fmaxf(dn * acc.z + bb.z, 0.f);
    o.w = fmaxf(dn * acc.w + bb.w, 0.f);

    if (!FUSE3) {
        *(float4*)(out + (size_t)node * 64 + c) = o;
    } else {
        float4 w0 = *(const float4*)(W3 + c * 2);
        float4 w1 = *(const float4*)(W3 + c * 2 + 4);
        float p0 = o.x * w0.x + o.y * w0.z + o.z * w1.x + o.w * w1.z;
        float p1 = o.x * w0.y + o.y * w0.w + o.z * w1.y + o.w * w1.w;
        unsigned hm = 0xFFFFu << (threadIdx.x & 16);
        #pragma unroll
        for (int off = 8; off > 0; off >>= 1) {
            p0 += __shfl_xor_sync(hm, p0, off, 16);
            p1 += __shfl_xor_sync(hm, p1, off, 16);
        }
        if (lane16 == 0) {
            h3[2 * (size_t)node + 0] = p0 * dn;
            h3[2 * (size_t)node + 1] = p1 * dn;
        }
    }
}

// -------------------- layer 3: pull (2 feats) + log_softmax, 1 thread/node --------------------
__global__ void k_pull2_final(const int* __restrict__ rstart, const int* __restrict__ degi,
                              const int* __restrict__ csr, const float* __restrict__ h3,
                              const float* __restrict__ dinv, const float* __restrict__ b3,
                              float* __restrict__ out, int n) {
    int i = blockIdx.x * blockDim.x + threadIdx.x;
    if (i >= n) return;
    int s0  = __ldg(&rstart[i]);
    int cnt = __ldg(&degi[i]);

    float2 self = *(const float2*)(h3 + (size_t)i * 2);
    float a0 = self.x, a1 = self.y;

    int e = 0;
    for (; e + 4 <= cnt; e += 4) {
        int u0 = __ldg(&csr[s0 + e + 0]);
        int u1 = __ldg(&csr[s0 + e + 1]);
        int u2 = __ldg(&csr[s0 + e + 2]);
        int u3 = __ldg(&csr[s0 + e + 3]);
        float2 v0 = *(const float2*)(h3 + (size_t)u0 * 2);
        float2 v1 = *(const float2*)(h3 + (size_t)u1 * 2);
        float2 v2 = *(const float2*)(h3 + (size_t)u2 * 2);
        float2 v3 = *(const float2*)(h3 + (size_t)u3 * 2);
        a0 += v0.x + v1.x + v2.x + v3.x;
        a1 += v0.y + v1.y + v2.y + v3.y;
    }
    for (; e < cnt; e++) {
        int u = __ldg(&csr[s0 + e]);
        float2 v = *(const float2*)(h3 + (size_t)u * 2);
        a0 += v.x; a1 += v.y;
    }

    float d  = dinv[i];
    float o0 = d * a0 + b3[0];
    float o1 = d * a1 + b3[1];
    float m  = fmaxf(o0, o1);
    float lse = m + logf(expf(o0 - m) + expf(o1 - m));
    out[2 * i + 0] = o0 - lse;
    out[2 * i + 1] = o1 - lse;
}

// -------------------- launch (single stream, serial) --------------------
extern "C" void kernel_launch(void* const* d_in, const int* in_sizes, int n_in,
                              void* d_out, int out_size) {
    const float* x  = (const float*)d_in[0];
    const int*   ei = (const int*)  d_in[1];
    const float* W1 = (const float*)d_in[2];
    const float* b1 = (const float*)d_in[3];
    const float* W2 = (const float*)d_in[4];
    const float* b2 = (const float*)d_in[5];
    const float* W3 = (const float*)d_in[6];
    const float* b3 = (const float*)d_in[7];

    const int N = in_sizes[0] / F_IN;
    const int E = in_sizes[1] / 2;
    const int* src = ei;
    const int* dst = ei + E;

    int *degi, *rstart, *cursor, *bsum, *csr;
    float *dinv, *x2, *h3;
    __half* h;
    cudaGetSymbolAddress((void**)&degi,   g_degi);
    cudaGetSymbolAddress((void**)&rstart, g_rstart);
    cudaGetSymbolAddress((void**)&cursor, g_cursor);
    cudaGetSymbolAddress((void**)&bsum,   g_bsum);
    cudaGetSymbolAddress((void**)&csr,    g_csr);
    cudaGetSymbolAddress((void**)&dinv,   g_dinv);
    cudaGetSymbolAddress((void**)&h,      g_h);
    cudaGetSymbolAddress((void**)&x2,     g_x2);
    cudaGetSymbolAddress((void**)&h3,     g_h3);

    const int T  = 256;
    const int NB = (N + 255) / 256;
    const int gemm_blocks = (N + 63) / 64;
    const int pull_blocks = (N * 16 + T - 1) / T;

    // prep start (independent of gemm1)
    k_zero_deg  <<<(N + T - 1) / T, T>>>(degi, N);
    k_count_deg <<<(E + T - 1) / T, T>>>(dst, degi, E);
    k_scan_block<<<NB, 256>>>(degi, rstart, bsum, N);

    // layer-1 GEMM (tf32 tc, BM=64, UNSCALED, fp16 out) — submission 4 = ncu slot
    k_gemm_tc<F_IN, false><<<gemm_blocks, T>>>(x, W1, nullptr, h, N);

    // prep finish
    k_add_off   <<<NB, 256>>>(rstart, cursor, bsum, degi, dinv, N);
    k_build_csr <<<(E + T - 1) / T, T>>>(src, dst, cursor, csr, E);

    // ---- layer 1 aggregation (neighbor-scaled pull over fp16 h) ----
    k_pull64<true, false><<<pull_blocks, T>>>(rstart, degi, csr, h, dinv, b1,
                                              nullptr, x2, nullptr, N);

    // ---- layer 2 (tf32 tc, dinv-scaled, fp16 out) + pull with fused layer-3 linear ----
    k_gemm_tc<HID, true><<<gemm_blocks, T>>>(x2, W2, dinv, h, N);
    k_pull64<false, true><<<pull_blocks, T>>>(rstart, degi, csr, h, dinv, b2,
                                              W3, nullptr, h3, N);

    // ---- layer 3 aggregation + log_softmax ----
    k_pull2_final<<<(N + T - 1) / T, T>>>(rstart, degi, csr, h3, dinv, b3, (float*)d_out, N);
}

// round 13
// speedup vs baseline: 1.0362x; 1.0362x over previous
#include <cuda_runtime.h>
#include <cuda_fp16.h>
#include <cstdint>
#include <cstring>
#include <math.h>

#define N_NODES 100000
#define N_EDGES 1600000
#define F_IN    256
#define HID     64

// -------- scratch (no device allocations allowed) --------
__device__ int    g_degi  [N_NODES];
__device__ float  g_dinv  [N_NODES];
__device__ int    g_rstart[N_NODES];
__device__ int    g_cursor[N_NODES];
__device__ int    g_bsum  [512];
__device__ int    g_csr   [N_EDGES];
__device__ __half g_h     [(size_t)N_NODES * HID];   // fp16 feature table (gather-optimized)
__device__ __half g_x2h   [(size_t)N_NODES * HID];   // fp16 activations (layer-2 input)
__device__ float  g_h3    [(size_t)N_NODES * 2];

// register-safe packed-half2 -> float2 (memcpy bitcast always lowers to mov)
__device__ __forceinline__ float2 h2f2(uint32_t u) {
    __half2 h;
    memcpy(&h, &u, 4);
    return __half22float2(h);
}

// -------------------- degree --------------------
__global__ void k_count_deg(const int* __restrict__ dst, int* __restrict__ deg, int e) {
    int i = blockIdx.x * blockDim.x + threadIdx.x;
    if (i < e) atomicAdd(&deg[dst[i]], 1);
}

// -------------------- block-level exclusive scan over deg --------------------
__global__ void k_scan_block(const int* __restrict__ deg, int* __restrict__ rstart,
                             int* __restrict__ bsum, int n) {
    __shared__ int sm[256];
    int i = blockIdx.x * 256 + threadIdx.x;
    int v = (i < n) ? deg[i] : 0;
    sm[threadIdx.x] = v;
    __syncthreads();
    #pragma unroll
    for (int off = 1; off < 256; off <<= 1) {
        int t = (threadIdx.x >= off) ? sm[threadIdx.x - off] : 0;
        __syncthreads();
        sm[threadIdx.x] += t;
        __syncthreads();
    }
    if (i < n) rstart[i] = sm[threadIdx.x] - v;       // exclusive within block
    if (threadIdx.x == 255) bsum[blockIdx.x] = sm[255];
}

// add per-block global offset (reduced from raw bsum) + init cursor + dinv (fused)
__global__ void k_add_off(int* __restrict__ rstart, int* __restrict__ cursor,
                          const int* __restrict__ bsum, const int* __restrict__ degi,
                          float* __restrict__ dinv, int n) {
    __shared__ int sm[256];
    int b = blockIdx.x;
    int t = threadIdx.x;
    int v = 0;
    for (int j = t; j < b; j += 256) v += bsum[j];
    sm[t] = v;
    __syncthreads();
    #pragma unroll
    for (int off = 128; off > 0; off >>= 1) {
        if (t < off) sm[t] += sm[t + off];
        __syncthreads();
    }
    int off0 = sm[0];
    int i = b * 256 + t;
    if (i < n) {
        int val = rstart[i] + off0;
        rstart[i] = val;
        cursor[i] = val;
        dinv[i] = rsqrtf((float)(degi[i] + 1));   // +1 self-loop
    }
}

__global__ void k_build_csr(const int* __restrict__ src, const int* __restrict__ dst,
                            int* __restrict__ cursor, int* __restrict__ csr, int e) {
    int i = blockIdx.x * blockDim.x + threadIdx.x;
    if (i < e) {
        int p = atomicAdd(&cursor[dst[i]], 1);
        csr[p] = src[i];
    }
}

// -------------------- helpers for tf32 MMA --------------------
__device__ __forceinline__ uint32_t f2tf32(float f) {
    uint32_t u;
    asm("cvt.rna.tf32.f32 %0, %1;" : "=r"(u) : "f"(f));
    return u;
}
__device__ __forceinline__ uint4 cvt4(float4 v) {
    return make_uint4(f2tf32(v.x), f2tf32(v.y), f2tf32(v.z), f2tf32(v.w));
}

// A-tile loader: 4 consecutive elements -> float4 (fp32 direct, fp16 convert)
__device__ __forceinline__ float4 loadA4(const float* p) {
    return *(const float4*)p;
}
__device__ __forceinline__ float4 loadA4(const __half* p) {
    uint2 raw = *(const uint2*)p;
    float2 f01 = h2f2(raw.x);
    float2 f23 = h2f2(raw.y);
    return make_float4(f01.x, f01.y, f23.x, f23.y);
}

// -------------------- tf32 tensor-core GEMM (R11-proven, BM=128) -----------------------
// hout[m,0:64] = half( (A[m,:]@W) * (SCALED ? dinv[m] : 1) )
// BM=128, BN=64, BK=32; 256 threads = 8 warps (4 M x 2 N), warp tile 32x32.
// __launch_bounds__(256, 2): 128-reg cap -> 2 CTAs/SM. Register prefetch of next k-tile.
template <int K, bool SCALED, typename AT>
__global__ __launch_bounds__(256, 2) void k_gemm_tc(
        const AT* __restrict__ A, const float* __restrict__ W,
        const float* __restrict__ dinv, __half* __restrict__ hout, int M) {
    __shared__ uint32_t As[128][36];   // [m][k], stride 36: conflict-free frags
    __shared__ uint32_t Bs[32][72];    // [k][n], stride 72: conflict-free frags

    const int tid  = threadIdx.x;
    const int lane = tid & 31;
    const int warp = tid >> 5;
    const int wm   = warp & 3;         // M warp 0..3 (32 rows each)
    const int wn   = warp >> 2;        // N warp 0..1 (32 cols each)
    const int g    = lane >> 2;        // groupID 0..7
    const int t    = lane & 3;         // thread-in-group 0..3
    const int row0 = blockIdx.x * 128;

    int am[4], ak[4];
    #pragma unroll
    for (int l = 0; l < 4; l++) {
        int i = tid + l * 256;
        am[l] = i >> 3;
        ak[l] = (i & 7) << 2;
    }
    int bk[2], bn[2];
    #pragma unroll
    for (int l = 0; l < 2; l++) {
        int i = tid + l * 256;
        bk[l] = i >> 4;
        bn[l] = (i & 15) << 2;
    }

    float4 ra[4], rb[2];
    float c[2][4][4] = {};

    #pragma unroll
    for (int l = 0; l < 4; l++) {
        int gr = row0 + am[l];
        ra[l] = (gr < M) ? loadA4(A + (size_t)gr * K + ak[l])
                         : make_float4(0.f, 0.f, 0.f, 0.f);
    }
    #pragma unroll
    for (int l = 0; l < 2; l++)
        rb[l] = *(const float4*)(W + (size_t)bk[l] * 64 + bn[l]);

    constexpr int NT = K / 32;
    #pragma unroll
    for (int kt = 0; kt < NT; kt++) {
        #pragma unroll
        for (int l = 0; l < 4; l++)
            *(uint4*)&As[am[l]][ak[l]] = cvt4(ra[l]);
        #pragma unroll
        for (int l = 0; l < 2; l++)
            *(uint4*)&Bs[bk[l]][bn[l]] = cvt4(rb[l]);
        __syncthreads();

        if (kt + 1 < NT) {
            int k0 = (kt + 1) * 32;
            #pragma unroll
            for (int l = 0; l < 4; l++) {
                int gr = row0 + am[l];
                ra[l] = (gr < M) ? loadA4(A + (size_t)gr * K + k0 + ak[l])
                                 : make_float4(0.f, 0.f, 0.f, 0.f);
            }
            #pragma unroll
            for (int l = 0; l < 2; l++)
                rb[l] = *(const float4*)(W + (size_t)(k0 + bk[l]) * 64 + bn[l]);
        }

        #pragma unroll
        for (int kc = 0; kc < 4; kc++) {
            int kb = kc * 8;
            uint32_t a[2][4];
            #pragma unroll
            for (int mt = 0; mt < 2; mt++) {
                int mb = wm * 32 + mt * 16;
                a[mt][0] = As[mb + g     ][kb + t    ];
                a[mt][1] = As[mb + g + 8 ][kb + t    ];
                a[mt][2] = As[mb + g     ][kb + t + 4];
                a[mt][3] = As[mb + g + 8 ][kb + t + 4];
            }
            uint32_t bfr[4][2];
            #pragma unroll
            for (int j = 0; j < 4; j++) {
                int nb = wn * 32 + j * 8;
                bfr[j][0] = Bs[kb + t    ][nb + g];
                bfr[j][1] = Bs[kb + t + 4][nb + g];
            }
            #pragma unroll
            for (int mt = 0; mt < 2; mt++) {
                #pragma unroll
                for (int j = 0; j < 4; j++) {
                    asm volatile(
                        "mma.sync.aligned.m16n8k8.row.col.f32.tf32.tf32.f32 "
                        "{%0,%1,%2,%3}, {%4,%5,%6,%7}, {%8,%9}, {%0,%1,%2,%3};"
                        : "+f"(c[mt][j][0]), "+f"(c[mt][j][1]),
                          "+f"(c[mt][j][2]), "+f"(c[mt][j][3])
                        : "r"(a[mt][0]), "r"(a[mt][1]), "r"(a[mt][2]), "r"(a[mt][3]),
                          "r"(bfr[j][0]), "r"(bfr[j][1]));
                }
            }
        }
        __syncthreads();
    }

    // epilogue: fp16 stores. c0,c1 -> row g; c2,c3 -> row g+8; cols 2t, 2t+1
    #pragma unroll
    for (int mt = 0; mt < 2; mt++) {
        int r0 = row0 + wm * 32 + mt * 16 + g;
        float d0 = (SCALED && r0 < M)     ? dinv[r0]     : 1.0f;
        float d1 = (SCALED && r0 + 8 < M) ? dinv[r0 + 8] : 1.0f;
        #pragma unroll
        for (int j = 0; j < 4; j++) {
            int col = wn * 32 + j * 8 + 2 * t;
            if (r0 < M)
                *(__half2*)(hout + (size_t)r0 * 64 + col) =
                    __floats2half2_rn(c[mt][j][0] * d0, c[mt][j][1] * d0);
            if (r0 + 8 < M)
                *(__half2*)(hout + (size_t)(r0 + 8) * 64 + col) =
                    __floats2half2_rn(c[mt][j][2] * d1, c[mt][j][3] * d1);
        }
    }
}

// -------------------- pull aggregation + fused epilogue (64 fp16 features) ----------------
// 16 threads per node, 4 features each (8B per lane -> 128B per edge); fp32 accumulators.
// NSCALE=true:  h is UNSCALED (layer 1): neighbor rows scaled by dinv[u], self by dinv[node].
// FUSE3=false:  write relu'd row to fp16 table `out`.
// FUSE3=true:   compute h3[node][0:2] = (relu_row @ W3) * dinv[node] via 16-lane shfl.
template <bool NSCALE, bool FUSE3>
__global__ void k_pull64(const int* __restrict__ rstart, const int* __restrict__ degi,
                         const int* __restrict__ csr, const __half* __restrict__ h,
                         const float* __restrict__ dinv, const float* __restrict__ b,
                         const float* __restrict__ W3, __half* __restrict__ out,
                         float* __restrict__ h3, int n) {
    int gid  = blockIdx.x * blockDim.x + threadIdx.x;
    int node = gid >> 4;
    if (node >= n) return;
    int lane16 = gid & 15;
    int c = lane16 << 2;

    int s0  = __ldg(&rstart[node]);
    int cnt = __ldg(&degi[node]);
    float dn = dinv[node];

    // self-loop term
    float4 acc;
    {
        uint2 raw = *(const uint2*)(h + (size_t)node * 64 + c);
        float2 f01 = h2f2(raw.x);
        float2 f23 = h2f2(raw.y);
        acc = make_float4(f01.x, f01.y, f23.x, f23.y);
    }
    if (NSCALE) { acc.x *= dn; acc.y *= dn; acc.z *= dn; acc.w *= dn; }

    int e = 0;
    for (; e + 4 <= cnt; e += 4) {
        int u0 = __ldg(&csr[s0 + e + 0]);
        int u1 = __ldg(&csr[s0 + e + 1]);
        int u2 = __ldg(&csr[s0 + e + 2]);
        int u3 = __ldg(&csr[s0 + e + 3]);
        uint2 r0 = *(const uint2*)(h + (size_t)u0 * 64 + c);
        uint2 r1 = *(const uint2*)(h + (size_t)u1 * 64 + c);
        uint2 r2 = *(const uint2*)(h + (size_t)u2 * 64 + c);
        uint2 r3 = *(const uint2*)(h + (size_t)u3 * 64 + c);
        float2 a01 = h2f2(r0.x), a23 = h2f2(r0.y);
        float2 b01 = h2f2(r1.x), b23 = h2f2(r1.y);
        float2 c01 = h2f2(r2.x), c23 = h2f2(r2.y);
        float2 d01 = h2f2(r3.x), d23 = h2f2(r3.y);
        if (NSCALE) {
            float s0f = __ldg(&dinv[u0]), s1f = __ldg(&dinv[u1]);
            float s2f = __ldg(&dinv[u2]), s3f = __ldg(&dinv[u3]);
            acc.x += a01.x * s0f + b01.x * s1f + c01.x * s2f + d01.x * s3f;
            acc.y += a01.y * s0f + b01.y * s1f + c01.y * s2f + d01.y * s3f;
            acc.z += a23.x * s0f + b23.x * s1f + c23.x * s2f + d23.x * s3f;
            acc.w += a23.y * s0f + b23.y * s1f + c23.y * s2f + d23.y * s3f;
        } else {
            acc.x += a01.x + b01.x + c01.x + d01.x;
            acc.y += a01.y + b01.y + c01.y + d01.y;
            acc.z += a23.x + b23.x + c23.x + d23.x;
            acc.w += a23.y + b23.y + c23.y + d23.y;
        }
    }
    for (; e < cnt; e++) {
        int u = __ldg(&csr[s0 + e]);
        uint2 raw = *(const uint2*)(h + (size_t)u * 64 + c);
        float2 f01 = h2f2(raw.x);
        float2 f23 = h2f2(raw.y);
        float d = NSCALE ? __ldg(&dinv[u]) : 1.0f;
        acc.x += f01.x * d; acc.y += f01.y * d; acc.z += f23.x * d; acc.w += f23.y * d;
    }

    float4 bb = *(const float4*)(b + c);
    float4 o;
    o.x = fmaxf(dn * acc.x + bb.x, 0.f);
    o.y = fmaxf(dn * acc.y + bb.y, 0.f);
    o.z = fmaxf(dn * acc.z + bb.z, 0.f);
    o.w = fmaxf(dn * acc.w + bb.w, 0.f);

    if (!FUSE3) {
        __half2 p0 = __floats2half2_rn(o.x, o.y);
        __half2 p1 = __floats2half2_rn(o.z, o.w);
        uint2 packed;
        memcpy(&packed.x, &p0, 4);
        memcpy(&packed.y, &p1, 4);
        *(uint2*)(out + (size_t)node * 64 + c) = packed;
    } else {
        float4 w0 = *(const float4*)(W3 + c * 2);
        float4 w1 = *(const float4*)(W3 + c * 2 + 4);
        float p0 = o.x * w0.x + o.y * w0.z + o.z * w1.x + o.w * w1.z;
        float p1 = o.x * w0.y + o.y * w0.w + o.z * w1.y + o.w * w1.w;
        unsigned hm = 0xFFFFu << (threadIdx.x & 16);
        #pragma unroll
        for (int off = 8; off > 0; off >>= 1) {
            p0 += __shfl_xor_sync(hm, p0, off, 16);
            p1 += __shfl_xor_sync(hm, p1, off, 16);
        }
        if (lane16 == 0) {
            h3[2 * (size_t)node + 0] = p0 * dn;
            h3[2 * (size_t)node + 1] = p1 * dn;
        }
    }
}

// -------------------- layer 3: pull (2 feats) + log_softmax, 1 thread/node --------------------
__global__ void k_pull2_final(const int* __restrict__ rstart, const int* __restrict__ degi,
                              const int* __restrict__ csr, const float* __restrict__ h3,
                              const float* __restrict__ dinv, const float* __restrict__ b3,
                              float* __restrict__ out, int n) {
    int i = blockIdx.x * blockDim.x + threadIdx.x;
    if (i >= n) return;
    int s0  = __ldg(&rstart[i]);
    int cnt = __ldg(&degi[i]);

    float2 self = *(const float2*)(h3 + (size_t)i * 2);
    float a0 = self.x, a1 = self.y;

    int e = 0;
    for (; e + 4 <= cnt; e += 4) {
        int u0 = __ldg(&csr[s0 + e + 0]);
        int u1 = __ldg(&csr[s0 + e + 1]);
        int u2 = __ldg(&csr[s0 + e + 2]);
        int u3 = __ldg(&csr[s0 + e + 3]);
        float2 v0 = *(const float2*)(h3 + (size_t)u0 * 2);
        float2 v1 = *(const float2*)(h3 + (size_t)u1 * 2);
        float2 v2 = *(const float2*)(h3 + (size_t)u2 * 2);
        float2 v3 = *(const float2*)(h3 + (size_t)u3 * 2);
        a0 += v0.x + v1.x + v2.x + v3.x;
        a1 += v0.y + v1.y + v2.y + v3.y;
    }
    for (; e < cnt; e++) {
        int u = __ldg(&csr[s0 + e]);
        float2 v = *(const float2*)(h3 + (size_t)u * 2);
        a0 += v.x; a1 += v.y;
    }

    float d  = dinv[i];
    float o0 = d * a0 + b3[0];
    float o1 = d * a1 + b3[1];
    float m  = fmaxf(o0, o1);
    float lse = m + logf(expf(o0 - m) + expf(o1 - m));
    out[2 * i + 0] = o0 - lse;
    out[2 * i + 1] = o1 - lse;
}

// -------------------- launch (single stream, serial) --------------------
extern "C" void kernel_launch(void* const* d_in, const int* in_sizes, int n_in,
                              void* d_out, int out_size) {
    const float* x  = (const float*)d_in[0];
    const int*   ei = (const int*)  d_in[1];
    const float* W1 = (const float*)d_in[2];
    const float* b1 = (const float*)d_in[3];
    const float* W2 = (const float*)d_in[4];
    const float* b2 = (const float*)d_in[5];
    const float* W3 = (const float*)d_in[6];
    const float* b3 = (const float*)d_in[7];

    const int N = in_sizes[0] / F_IN;
    const int E = in_sizes[1] / 2;
    const int* src = ei;
    const int* dst = ei + E;

    int *degi, *rstart, *cursor, *bsum, *csr;
    float *dinv, *h3;
    __half *h, *x2h;
    cudaGetSymbolAddress((void**)&degi,   g_degi);
    cudaGetSymbolAddress((void**)&rstart, g_rstart);
    cudaGetSymbolAddress((void**)&cursor, g_cursor);
    cudaGetSymbolAddress((void**)&bsum,   g_bsum);
    cudaGetSymbolAddress((void**)&csr,    g_csr);
    cudaGetSymbolAddress((void**)&dinv,   g_dinv);
    cudaGetSymbolAddress((void**)&h,      g_h);
    cudaGetSymbolAddress((void**)&x2h,    g_x2h);
    cudaGetSymbolAddress((void**)&h3,     g_h3);

    const int T  = 256;
    const int NB = (N + 255) / 256;
    const int gemm_blocks = (N + 127) / 128;
    const int pull_blocks = (N * 16 + T - 1) / T;

    // prep start (independent of gemm1); memset node replaces zero kernel
    cudaMemsetAsync(degi, 0, (size_t)N * sizeof(int));
    k_count_deg <<<(E + T - 1) / T, T>>>(dst, degi, E);
    k_scan_block<<<NB, 256>>>(degi, rstart, bsum, N);

    // layer-1 GEMM (tf32 tc, BM=128, UNSCALED, fp32 in / fp16 out)
    k_gemm_tc<F_IN, false, float><<<gemm_blocks, T>>>(x, W1, nullptr, h, N);

    // prep finish
    k_add_off   <<<NB, 256>>>(rstart, cursor, bsum, degi, dinv, N);
    k_build_csr <<<(E + T - 1) / T, T>>>(src, dst, cursor, csr, E);

    // ---- layer 1 aggregation (neighbor-scaled pull over fp16 h, fp16 x2 out) ----
    k_pull64<true, false><<<pull_blocks, T>>>(rstart, degi, csr, h, dinv, b1,
                                              nullptr, x2h, nullptr, N);

    // ---- layer 2 (tf32 tc, fp16 in / fp16 out, dinv-scaled) + pull with fused L3 linear ----
    k_gemm_tc<HID, true, __half><<<gemm_blocks, T>>>(x2h, W2, dinv, h, N);
    k_pull64<false, true><<<pull_blocks, T>>>(rstart, degi, csr, h, dinv, b2,
                                              W3, nullptr, h3, N);

    // ---- layer 3 aggregation + log_softmax ----
    k_pull2_final<<<(N + T - 1) / T, T>>>(rstart, degi, csr, h3, dinv, b3, (float*)d_out, N);
}